// round 1
// baseline (speedup 1.0000x reference)
#include <cuda_runtime.h>

#define D      128
#define D4     32          // D/4
#define MAXN   100000
#define MAXE   1600000
#define SCAN_B 1024
#define GR     64          // GEMM rows per block

// ---------------- scratch (no allocation allowed; __device__ globals) ----------
__device__ int       g_cnt[MAXN];
__device__ int       g_rowptr[MAXN + 1];
__device__ int       g_fill[MAXN];
__device__ float     g_dis[MAXN];
__device__ int       g_bsum[256];
__device__ int       g_boff[256];
__device__ long long g_csr[MAXE];                 // [norm(f32)<<32 | src]
__device__ float     g_buf0[(size_t)MAXN * D];
__device__ float     g_buf1[(size_t)MAXN * D];

// ---------------- graph preprocessing ----------------

__global__ void k_zero(int n) {
    int i = blockIdx.x * blockDim.x + threadIdx.x;
    if (i < n) g_cnt[i] = 0;
}

__global__ void k_hist(const int* __restrict__ dst, int e) {
    int i = blockIdx.x * blockDim.x + threadIdx.x;
    if (i < e) atomicAdd(&g_cnt[dst[i]], 1);
}

__global__ void k_dis(int n) {
    int i = blockIdx.x * blockDim.x + threadIdx.x;
    if (i < n) g_dis[i] = rsqrtf((float)(g_cnt[i] + 1));   // deg includes self-loop, >=1
}

__global__ void k_bsum(int n) {
    __shared__ int s[SCAN_B];
    int t = threadIdx.x;
    int i = blockIdx.x * SCAN_B + t;
    s[t] = (i < n) ? g_cnt[i] : 0;
    __syncthreads();
    for (int off = SCAN_B / 2; off > 0; off >>= 1) {
        if (t < off) s[t] += s[t + off];
        __syncthreads();
    }
    if (t == 0) g_bsum[blockIdx.x] = s[0];
}

__global__ void k_scanb(int nb) {
    __shared__ int s[256];
    int t = threadIdx.x;
    if (t < nb) s[t] = g_bsum[t];
    __syncthreads();
    if (t == 0) {
        int run = 0;
        for (int j = 0; j < nb; j++) { int v = s[j]; s[j] = run; run += v; }
    }
    __syncthreads();
    if (t < nb) g_boff[t] = s[t];
}

__global__ void k_scan(int n, int e) {
    __shared__ int s[SCAN_B];
    int t = threadIdx.x;
    int i = blockIdx.x * SCAN_B + t;
    int v = (i < n) ? g_cnt[i] : 0;
    s[t] = v;
    __syncthreads();
    for (int off = 1; off < SCAN_B; off <<= 1) {
        int x = (t >= off) ? s[t - off] : 0;
        __syncthreads();
        s[t] += x;
        __syncthreads();
    }
    if (i < n) {
        int ex = g_boff[blockIdx.x] + s[t] - v;   // exclusive prefix
        g_rowptr[i] = ex;
        g_fill[i]   = ex;
    }
    if (i == 0) g_rowptr[n] = e;
}

__global__ void k_fill(const int* __restrict__ src, const int* __restrict__ dst, int e) {
    int i = blockIdx.x * blockDim.x + threadIdx.x;
    if (i >= e) return;
    int s = src[i], d = dst[i];
    int p = atomicAdd(&g_fill[d], 1);
    float nm = g_dis[s] * g_dis[d];
    long long pk = ((long long)__float_as_int(nm) << 32) | (unsigned int)s;
    g_csr[p] = pk;
}

// ---------------- GEMM: Y[n,128] = X[n,128] @ W[128,128] ----------------
// W fully in smem (64KB) + 64-row X tile (32KB). Each thread: 8 rows x 4 cols.
__global__ void __launch_bounds__(256, 2)
k_gemm(const float* __restrict__ X, const float* __restrict__ W,
       float* __restrict__ Y, int n) {
    extern __shared__ float sm[];
    float* sW = sm;            // D*D
    float* sX = sm + D * D;    // GR*D
    int t = threadIdx.x;
    int rowBase = blockIdx.x * GR;

    {   // load W (4096 float4)
        float4* sW4 = (float4*)sW;
        const float4* W4 = (const float4*)W;
        for (int i = t; i < D * D / 4; i += 256) sW4[i] = W4[i];
    }
    {   // load X tile (2048 float4), zero-pad tail rows
        float4* sX4 = (float4*)sX;
        const float4* X4 = (const float4*)X;
        for (int i = t; i < GR * D / 4; i += 256) {
            int r = rowBase + i / D4;
            sX4[i] = (r < n) ? X4[(size_t)r * D4 + (i % D4)]
                             : make_float4(0.f, 0.f, 0.f, 0.f);
        }
    }
    __syncthreads();

    int lane = t & 31;     // float4 col group: cols lane*4 .. lane*4+3
    int wid  = t >> 5;     // row stream 0..7 (rows wid + 8*i)
    float4 acc[8];
#pragma unroll
    for (int i = 0; i < 8; i++) acc[i] = make_float4(0.f, 0.f, 0.f, 0.f);

    const float4* sW4 = (const float4*)sW;
#pragma unroll 4
    for (int k = 0; k < D; k++) {
        float4 w = sW4[k * D4 + lane];
#pragma unroll
        for (int i = 0; i < 8; i++) {
            float xv = sX[(wid + i * 8) * D + k];   // warp-uniform broadcast
            acc[i].x += xv * w.x;
            acc[i].y += xv * w.y;
            acc[i].z += xv * w.z;
            acc[i].w += xv * w.w;
        }
    }

    float4* Y4 = (float4*)Y;
#pragma unroll
    for (int i = 0; i < 8; i++) {
        int r = rowBase + wid + i * 8;
        if (r < n) Y4[(size_t)r * D4 + lane] = acc[i];
    }
}

// ---------------- aggregation: out[v] = act( sum_e norm*T[src] + selfnorm*T[v] + b )
// one warp per node, float4 per lane (lane covers cols lane*4..lane*4+3)
__global__ void k_agg(const float4* __restrict__ T, const float* __restrict__ bias,
                      float4* __restrict__ O, int n, int relu) {
    int gw = (blockIdx.x * blockDim.x + threadIdx.x) >> 5;
    if (gw >= n) return;
    int lane = threadIdx.x & 31;

    float dv = g_dis[gw];
    float sn = dv * dv;                 // self-loop norm = 1/deg
    float4 a = T[(size_t)gw * D4 + lane];
    float4 acc = make_float4(sn * a.x, sn * a.y, sn * a.z, sn * a.w);

    int beg = g_rowptr[gw], end = g_rowptr[gw + 1];
    for (int j = beg; j < end; j++) {
        long long pk = g_csr[j];        // warp-uniform broadcast load
        int   s  = (int)(pk & 0xffffffffLL);
        float nm = __int_as_float((int)(pk >> 32));
        float4 b = T[(size_t)s * D4 + lane];
        acc.x += nm * b.x;
        acc.y += nm * b.y;
        acc.z += nm * b.z;
        acc.w += nm * b.w;
    }

    float4 bb = ((const float4*)bias)[lane];
    acc.x += bb.x; acc.y += bb.y; acc.z += bb.z; acc.w += bb.w;
    if (relu) {
        acc.x = fmaxf(acc.x, 0.f);
        acc.y = fmaxf(acc.y, 0.f);
        acc.z = fmaxf(acc.z, 0.f);
        acc.w = fmaxf(acc.w, 0.f);
    }
    O[(size_t)gw * D4 + lane] = acc;
}

// ---------------- launch ----------------
extern "C" void kernel_launch(void* const* d_in, const int* in_sizes, int n_in,
                              void* d_out, int out_size) {
    const float* x  = (const float*)d_in[0];
    const int*   ei = (const int*)d_in[1];
    const float* W1 = (const float*)d_in[2];
    const float* b1 = (const float*)d_in[3];
    const float* W2 = (const float*)d_in[4];
    const float* b2 = (const float*)d_in[5];
    const float* W3 = (const float*)d_in[6];
    const float* b3 = (const float*)d_in[7];

    int n = in_sizes[0] / D;
    int e = in_sizes[1] / 2;
    const int* src = ei;
    const int* dst = ei + e;
    int nb = (n + SCAN_B - 1) / SCAN_B;

    // graph preprocessing
    k_zero <<<(n + 255) / 256, 256>>>(n);
    k_hist <<<(e + 255) / 256, 256>>>(dst, e);
    k_dis  <<<(n + 255) / 256, 256>>>(n);
    k_bsum <<<nb, SCAN_B>>>(n);
    k_scanb<<<1, 256>>>(nb);
    k_scan <<<nb, SCAN_B>>>(n, e);
    k_fill <<<(e + 255) / 256, 256>>>(src, dst, e);

    // buffers (device-symbol addresses; instantaneous API, capture-safe)
    void *p0 = nullptr, *p1 = nullptr;
    cudaGetSymbolAddress(&p0, g_buf0);
    cudaGetSymbolAddress(&p1, g_buf1);
    float* B0 = (float*)p0;
    float* B1 = (float*)p1;

    size_t smem = (size_t)(D * D + GR * D) * sizeof(float);   // 96KB
    cudaFuncSetAttribute(k_gemm, cudaFuncAttributeMaxDynamicSharedMemorySize, (int)smem);

    int gb = (n + GR - 1) / GR;
    int ab = (n + 7) / 8;        // 8 warps / block

    // layer 1
    k_gemm<<<gb, 256, smem>>>(x, W1, B0, n);
    k_agg <<<ab, 256>>>((const float4*)B0, b1, (float4*)B1, n, 1);
    // layer 2
    k_gemm<<<gb, 256, smem>>>(B1, W2, B0, n);
    k_agg <<<ab, 256>>>((const float4*)B0, b2, (float4*)B1, n, 1);
    // layer 3
    k_gemm<<<gb, 256, smem>>>(B1, W3, B0, n);
    k_agg <<<ab, 256>>>((const float4*)B0, b3, (float4*)d_out, n, 0);
}

// round 2
// speedup vs baseline: 1.2964x; 1.2964x over previous
#include <cuda_runtime.h>

#define D      128
#define D4     32          // D/4
#define MAXN   100000
#define MAXE   1600000
#define SCAN_B 1024
#define GR     64          // GEMM rows per block
#define XSTR   66          // transposed X tile stride (bank spread + 8B align)

// ---------------- scratch (no allocation allowed; __device__ globals) ----------
__device__ int       g_cnt[MAXN];
__device__ int       g_rowptr[MAXN + 1];
__device__ int       g_fill[MAXN];
__device__ float     g_dis[MAXN];
__device__ int       g_bsum[256];
__device__ int       g_boff[256];
__device__ long long g_csr[MAXE];                 // [norm(f32)<<32 | src]
__device__ float     g_buf0[(size_t)MAXN * D];
__device__ float     g_buf1[(size_t)MAXN * D];

// ---------------- f32x2 helpers ----------------
__device__ __forceinline__ unsigned long long pack2(float a, float b) {
    unsigned long long r;
    asm("mov.b64 %0, {%1, %2};" : "=l"(r) : "f"(a), "f"(b));
    return r;
}
__device__ __forceinline__ unsigned long long fma2(unsigned long long a,
                                                   unsigned long long b,
                                                   unsigned long long c) {
    unsigned long long d;
    asm("fma.rn.f32x2 %0, %1, %2, %3;" : "=l"(d) : "l"(a), "l"(b), "l"(c));
    return d;
}
__device__ __forceinline__ void unpack2(unsigned long long v, float& lo, float& hi) {
    asm("mov.b64 {%0, %1}, %2;" : "=f"(lo), "=f"(hi) : "l"(v));
}

// ---------------- graph preprocessing ----------------

__global__ void k_zero(int n) {
    int i = blockIdx.x * blockDim.x + threadIdx.x;
    if (i < n) g_cnt[i] = 0;
}

__global__ void k_hist(const int* __restrict__ dst, int e) {
    int i = blockIdx.x * blockDim.x + threadIdx.x;
    if (i < e) atomicAdd(&g_cnt[dst[i]], 1);
}

__global__ void k_dis(int n) {
    int i = blockIdx.x * blockDim.x + threadIdx.x;
    if (i < n) g_dis[i] = rsqrtf((float)(g_cnt[i] + 1));   // deg includes self-loop, >=1
}

__global__ void k_bsum(int n) {
    __shared__ int s[SCAN_B];
    int t = threadIdx.x;
    int i = blockIdx.x * SCAN_B + t;
    s[t] = (i < n) ? g_cnt[i] : 0;
    __syncthreads();
    for (int off = SCAN_B / 2; off > 0; off >>= 1) {
        if (t < off) s[t] += s[t + off];
        __syncthreads();
    }
    if (t == 0) g_bsum[blockIdx.x] = s[0];
}

__global__ void k_scanb(int nb) {
    __shared__ int s[256];
    int t = threadIdx.x;
    if (t < nb) s[t] = g_bsum[t];
    __syncthreads();
    if (t == 0) {
        int run = 0;
        for (int j = 0; j < nb; j++) { int v = s[j]; s[j] = run; run += v; }
    }
    __syncthreads();
    if (t < nb) g_boff[t] = s[t];
}

__global__ void k_scan(int n, int e) {
    __shared__ int s[SCAN_B];
    int t = threadIdx.x;
    int i = blockIdx.x * SCAN_B + t;
    int v = (i < n) ? g_cnt[i] : 0;
    s[t] = v;
    __syncthreads();
    for (int off = 1; off < SCAN_B; off <<= 1) {
        int x = (t >= off) ? s[t - off] : 0;
        __syncthreads();
        s[t] += x;
        __syncthreads();
    }
    if (i < n) {
        int ex = g_boff[blockIdx.x] + s[t] - v;   // exclusive prefix
        g_rowptr[i] = ex;
        g_fill[i]   = ex;
    }
    if (i == 0) g_rowptr[n] = e;
}

__global__ void k_fill(const int* __restrict__ src, const int* __restrict__ dst, int e) {
    int i = blockIdx.x * blockDim.x + threadIdx.x;
    if (i >= e) return;
    int s = src[i], d = dst[i];
    int p = atomicAdd(&g_fill[d], 1);
    float nm = g_dis[s] * g_dis[d];
    long long pk = ((long long)__float_as_int(nm) << 32) | (unsigned int)s;
    g_csr[p] = pk;
}

// ---------------- GEMM: Y[n,128] = X[n,128] @ W[128,128] ----------------
// W in smem row-major; X tile TRANSPOSED in smem (sXT[k*XSTR + r]) so that
// adjacent-row pairs load as packed 8B for fma.rn.f32x2 (FFMA2, 2x FMA rate).
// Each thread: 8 rows (4 packed pairs) x 4 cols = 16 FFMA2 per k.
__global__ void __launch_bounds__(256, 2)
k_gemm(const float* __restrict__ X, const float* __restrict__ W,
       float* __restrict__ Y, int n) {
    extern __shared__ float sm[];
    float* sW  = sm;               // D*D
    float* sXT = sm + D * D;       // D * XSTR
    int t = threadIdx.x;
    int rowBase = blockIdx.x * GR;

    {   // load W (4096 float4)
        float4* sW4 = (float4*)sW;
        const float4* W4 = (const float4*)W;
        for (int i = t; i < D * D / 4; i += 256) sW4[i] = W4[i];
    }
    {   // load X tile transposed: thread t handles column c = t%128, rows rh*32..
        int c  = t & (D - 1);
        int rh = t >> 7;           // 0 or 1
#pragma unroll
        for (int rr = 0; rr < GR / 2; rr++) {
            int r = rh * (GR / 2) + rr;
            int gr = rowBase + r;
            float v = (gr < n) ? X[(size_t)gr * D + c] : 0.f;
            sXT[c * XSTR + r] = v;
        }
    }
    __syncthreads();

    int lane = t & 31;     // float4 col group: cols lane*4 .. lane*4+3
    int wid  = t >> 5;     // warp handles rows [wid*8, wid*8+8) as 4 pairs

    unsigned long long acc[4][4];   // [pair j][col c] ; lo=row 2j, hi=row 2j+1
#pragma unroll
    for (int j = 0; j < 4; j++)
#pragma unroll
        for (int c = 0; c < 4; c++) acc[j][c] = 0ULL;

    const float4* sW4 = (const float4*)sW;
    int rbase = wid * 8;
#pragma unroll 4
    for (int k = 0; k < D; k++) {
        float4 w = sW4[k * D4 + lane];
        unsigned long long wx = pack2(w.x, w.x);
        unsigned long long wy = pack2(w.y, w.y);
        unsigned long long wz = pack2(w.z, w.z);
        unsigned long long ww = pack2(w.w, w.w);
        const float* xk = sXT + k * XSTR + rbase;
#pragma unroll
        for (int j = 0; j < 4; j++) {
            unsigned long long xp = *(const unsigned long long*)(xk + 2 * j);
            acc[j][0] = fma2(xp, wx, acc[j][0]);
            acc[j][1] = fma2(xp, wy, acc[j][1]);
            acc[j][2] = fma2(xp, wz, acc[j][2]);
            acc[j][3] = fma2(xp, ww, acc[j][3]);
        }
    }

    float4* Y4 = (float4*)Y;
#pragma unroll
    for (int j = 0; j < 4; j++) {
        float4 lo4, hi4;
        unpack2(acc[j][0], lo4.x, hi4.x);
        unpack2(acc[j][1], lo4.y, hi4.y);
        unpack2(acc[j][2], lo4.z, hi4.z);
        unpack2(acc[j][3], lo4.w, hi4.w);
        int r0 = rowBase + rbase + 2 * j;
        if (r0 < n)     Y4[(size_t)r0 * D4 + lane]       = lo4;
        if (r0 + 1 < n) Y4[(size_t)(r0 + 1) * D4 + lane] = hi4;
    }
}

// ---------------- aggregation: out[v] = act( sum_e norm*T[src] + selfnorm*T[v] + b )
// one warp per node, float4 per lane (lane covers cols lane*4..lane*4+3)
__global__ void k_agg(const float4* __restrict__ T, const float* __restrict__ bias,
                      float4* __restrict__ O, int n, int relu) {
    int gw = (blockIdx.x * blockDim.x + threadIdx.x) >> 5;
    if (gw >= n) return;
    int lane = threadIdx.x & 31;

    float dv = g_dis[gw];
    float sn = dv * dv;                 // self-loop norm = 1/deg
    float4 a = T[(size_t)gw * D4 + lane];
    float4 acc = make_float4(sn * a.x, sn * a.y, sn * a.z, sn * a.w);

    int beg = g_rowptr[gw], end = g_rowptr[gw + 1];
    for (int j = beg; j < end; j++) {
        long long pk = g_csr[j];        // warp-uniform broadcast load
        int   s  = (int)(pk & 0xffffffffLL);
        float nm = __int_as_float((int)(pk >> 32));
        float4 b = T[(size_t)s * D4 + lane];
        acc.x += nm * b.x;
        acc.y += nm * b.y;
        acc.z += nm * b.z;
        acc.w += nm * b.w;
    }

    float4 bb = ((const float4*)bias)[lane];
    acc.x += bb.x; acc.y += bb.y; acc.z += bb.z; acc.w += bb.w;
    if (relu) {
        acc.x = fmaxf(acc.x, 0.f);
        acc.y = fmaxf(acc.y, 0.f);
        acc.z = fmaxf(acc.z, 0.f);
        acc.w = fmaxf(acc.w, 0.f);
    }
    O[(size_t)gw * D4 + lane] = acc;
}

// ---------------- launch ----------------
extern "C" void kernel_launch(void* const* d_in, const int* in_sizes, int n_in,
                              void* d_out, int out_size) {
    const float* x  = (const float*)d_in[0];
    const int*   ei = (const int*)d_in[1];
    const float* W1 = (const float*)d_in[2];
    const float* b1 = (const float*)d_in[3];
    const float* W2 = (const float*)d_in[4];
    const float* b2 = (const float*)d_in[5];
    const float* W3 = (const float*)d_in[6];
    const float* b3 = (const float*)d_in[7];

    int n = in_sizes[0] / D;
    int e = in_sizes[1] / 2;
    const int* src = ei;
    const int* dst = ei + e;
    int nb = (n + SCAN_B - 1) / SCAN_B;

    // graph preprocessing
    k_zero <<<(n + 255) / 256, 256>>>(n);
    k_hist <<<(e + 255) / 256, 256>>>(dst, e);
    k_dis  <<<(n + 255) / 256, 256>>>(n);
    k_bsum <<<nb, SCAN_B>>>(n);
    k_scanb<<<1, 256>>>(nb);
    k_scan <<<nb, SCAN_B>>>(n, e);
    k_fill <<<(e + 255) / 256, 256>>>(src, dst, e);

    // buffers (device-symbol addresses; instantaneous API, capture-safe)
    void *p0 = nullptr, *p1 = nullptr;
    cudaGetSymbolAddress(&p0, g_buf0);
    cudaGetSymbolAddress(&p1, g_buf1);
    float* B0 = (float*)p0;
    float* B1 = (float*)p1;

    size_t smem = (size_t)(D * D + D * XSTR) * sizeof(float);   // ~97.8KB
    cudaFuncSetAttribute(k_gemm, cudaFuncAttributeMaxDynamicSharedMemorySize, (int)smem);

    int gb = (n + GR - 1) / GR;
    int ab = (n + 7) / 8;        // 8 warps / block

    // layer 1
    k_gemm<<<gb, 256, smem>>>(x, W1, B0, n);
    k_agg <<<ab, 256>>>((const float4*)B0, b1, (float4*)B1, n, 1);
    // layer 2
    k_gemm<<<gb, 256, smem>>>(B1, W2, B0, n);
    k_agg <<<ab, 256>>>((const float4*)B0, b2, (float4*)B1, n, 1);
    // layer 3
    k_gemm<<<gb, 256, smem>>>(B1, W3, B0, n);
    k_agg <<<ab, 256>>>((const float4*)B0, b3, (float4*)d_out, n, 0);
}